// round 15
// baseline (speedup 1.0000x reference)
#include <cuda_runtime.h>
#include <math.h>

#define BB 32
#define SS 64
#define TT 64
#define EE 512
#define HH 1024
#define H4 4096
#define VTV 32000
#define NBK 128

typedef unsigned long long ull;

// ---------------- scratch ----------------
__device__ float g_enc_xg[SS * BB * H4];
__device__ float g_dxg[(TT - 1) * BB * H4];
__device__ float g_enc_out[BB * SS * HH];
__device__ float g_enc_pre[BB * SS * HH];
__device__ float g_hhist[(TT - 1) * BB * HH];
__device__ float g_h[BB * HH];
__device__ float g_c[BB * HH];
__device__ float g_hw4[4 * BB * HH];
__device__ float g_sc[BB * SS];
__device__ float g_ctx[BB * HH];
__device__ float g_gates[BB * H4];
__device__ float g_encb[H4];
__device__ float g_decb[H4];
__device__ int   g_sidx[SS * BB];
__device__ int   g_tidx[(TT - 1) * BB];
__device__ unsigned g_cnt;   // zero-init; self-resetting
__device__ unsigned g_gen;   // monotonic

__device__ __forceinline__ float sigf(float x) { return 1.f / (1.f + expf(-x)); }
__device__ __forceinline__ float tanh_fast(float x) {
    float y; asm("tanh.approx.f32 %0, %1;" : "=f"(y) : "f"(x)); return y;
}
__device__ __forceinline__ void fma2(ull& acc, ull a, ull b) {
    asm("fma.rn.f32x2 %0, %1, %2, %0;" : "+l"(acc) : "l"(a), "l"(b));
}
__device__ __forceinline__ float lohi(ull a) {
    float2 v = *reinterpret_cast<float2*>(&a); return v.x + v.y;
}

// software grid barrier: all NBK blocks co-resident (1 block/SM via smem, grid<=SMs)
__device__ __forceinline__ void gbar()
{
    __syncthreads();
    if (threadIdx.x == 0) {
        unsigned my = *(volatile unsigned*)&g_gen;
        __threadfence();
        if (atomicAdd(&g_cnt, 1u) == NBK - 1u) {
            g_cnt = 0u;
            __threadfence();
            *(volatile unsigned*)&g_gen = my + 1u;
        } else {
            while (*(volatile unsigned*)&g_gen == my) __nanosleep(64);
        }
        __threadfence();
    }
    __syncthreads();
}

// ---------------- init ----------------
__global__ void init_kernel(float* __restrict__ out,
                            const int* __restrict__ src, const int* __restrict__ tgt,
                            const float* __restrict__ ebih, const float* __restrict__ ebhh,
                            const float* __restrict__ dbih, const float* __restrict__ dbhh)
{
    int idx = blockIdx.x * blockDim.x + threadIdx.x;
    if (idx < BB * VTV) {
        int b = idx / VTV, v = idx % VTV;
        out[(size_t)b * TT * VTV + v] = 0.f;
    }
    if (idx < BB * HH) g_h[idx] = 0.f;
    if (idx < SS * BB) { int s = idx >> 5, b = idx & 31; g_sidx[idx] = src[b * SS + s]; }
    if (idx < (TT - 1) * BB) { int d = idx >> 5, b = idx & 31; g_tidx[idx] = tgt[b * TT + d]; }
    if (idx < H4) {
        g_encb[idx] = ebih[idx] + ebhh[idx];
        g_decb[idx] = dbih[idx] + dbhh[idx];
    }
}

// ---------------- big NT GEMM (proven; fc + batched precomputes) ----------------
template<int EPI, bool GATHER>
__global__ void __launch_bounds__(256, 2)
gemm_big(const float* __restrict__ A, int lda,
         const float* __restrict__ Bw, int ldb,
         float* __restrict__ C, int ldc,
         int M, int N, int K,
         const float* __restrict__ bias,
         const int* __restrict__ gidx)
{
    constexpr int BM = 128, BN = 64, BK = 32, LDT = BK + 2;
    __shared__ __align__(16) float As[BM * LDT];
    __shared__ __align__(16) float Bs[BN * LDT];

    const int tid = threadIdx.x;
    const int bm = blockIdx.y * BM;
    const int bn = blockIdx.x * BN;
    const int tx = tid & 15;
    const int ty = tid >> 4;
    const int lr = tid >> 3, lc = (tid & 7) * 4;

    ull acc[8][4];
#pragma unroll
    for (int i = 0; i < 8; i++)
#pragma unroll
        for (int j = 0; j < 4; j++) acc[i][j] = 0ull;

    float4 pa[4], pb[2];
    const int KT = K / BK;

#define LOAD_TILE(k0)                                                           \
    {                                                                           \
        _Pragma("unroll")                                                       \
        for (int it = 0; it < 4; it++) {                                        \
            int r = lr + it * 32;                                               \
            int gm = bm + r; if (gm > M - 1) gm = M - 1;                        \
            const float* ar = GATHER ? (A + (size_t)gidx[gm] * lda)             \
                                     : (A + (size_t)gm * lda);                  \
            pa[it] = *reinterpret_cast<const float4*>(ar + (k0) + lc);          \
        }                                                                       \
        _Pragma("unroll")                                                       \
        for (int it = 0; it < 2; it++) {                                        \
            int r = lr + it * 32;                                               \
            pb[it] = *reinterpret_cast<const float4*>(Bw + (size_t)(bn + r) * ldb + (k0) + lc); \
        }                                                                       \
    }

    LOAD_TILE(0)
    for (int kt = 0; kt < KT; kt++) {
        __syncthreads();
#pragma unroll
        for (int it = 0; it < 4; it++) {
            int r = lr + it * 32;
            *reinterpret_cast<float2*>(&As[r * LDT + lc])     = make_float2(pa[it].x, pa[it].y);
            *reinterpret_cast<float2*>(&As[r * LDT + lc + 2]) = make_float2(pa[it].z, pa[it].w);
        }
#pragma unroll
        for (int it = 0; it < 2; it++) {
            int r = lr + it * 32;
            *reinterpret_cast<float2*>(&Bs[r * LDT + lc])     = make_float2(pb[it].x, pb[it].y);
            *reinterpret_cast<float2*>(&Bs[r * LDT + lc + 2]) = make_float2(pb[it].z, pb[it].w);
        }
        __syncthreads();
        if (kt + 1 < KT) LOAD_TILE((kt + 1) * BK)
#pragma unroll
        for (int kk = 0; kk < BK / 2; kk++) {
            ull av[8], bv[4];
#pragma unroll
            for (int i = 0; i < 8; i++)
                av[i] = *reinterpret_cast<const ull*>(&As[(ty + 16 * i) * LDT + 2 * kk]);
#pragma unroll
            for (int j = 0; j < 4; j++)
                bv[j] = *reinterpret_cast<const ull*>(&Bs[(tx + 16 * j) * LDT + 2 * kk]);
#pragma unroll
            for (int i = 0; i < 8; i++)
#pragma unroll
                for (int j = 0; j < 4; j++) fma2(acc[i][j], av[i], bv[j]);
        }
    }
#undef LOAD_TILE

#pragma unroll
    for (int i = 0; i < 8; i++) {
        int gm = bm + ty + 16 * i;
        if (gm >= M) continue;
#pragma unroll
        for (int j = 0; j < 4; j++) {
            float v = lohi(acc[i][j]);
            int gn = bn + tx + 16 * j;
            if (EPI == 0) {
                C[(size_t)gm * ldc + gn] = v;
            } else if (EPI == 1) {
                C[(size_t)gm * ldc + gn] = v + bias[gn];
            } else {
                int b = gm & 31, d = gm >> 5;
                C[((size_t)b * TT + d + 1) * VTV + gn] = v + bias[gn];
            }
        }
    }
}

// ---- 32x32-tile GEMM pass over K tiles; A staged from gmem (ldcg); W resident or staged
// acc[i][j] += sum_k A[ty+16i][k] * W[tx+16j][k].  All LDS are warp-broadcasts.
template<bool WRES>
__device__ __forceinline__ void gemm32(const float* __restrict__ Ag,
                                       const float* __restrict__ Wg, int ldw,
                                       float* Hs, const float* Ws, int wstr, float* Wcs,
                                       int kbeg, int nkt, ull acc[2][2], int tid)
{
    const int tx = tid & 15, ty = tid >> 4;
    const int sb = tid >> 3, sc = (tid & 7) * 4;
    for (int kt = 0; kt < nkt; kt++) {
        const int k0 = kbeg + kt * 32;
        __syncthreads();
        {
            float4 v = __ldcg(reinterpret_cast<const float4*>(Ag + (size_t)sb * HH + k0 + sc));
            *reinterpret_cast<float2*>(&Hs[sb * 34 + sc])     = make_float2(v.x, v.y);
            *reinterpret_cast<float2*>(&Hs[sb * 34 + sc + 2]) = make_float2(v.z, v.w);
            if (!WRES) {
                float4 w = *reinterpret_cast<const float4*>(Wg + (size_t)sb * ldw + k0 + sc);
                *reinterpret_cast<float2*>(&Wcs[sb * 34 + sc])     = make_float2(w.x, w.y);
                *reinterpret_cast<float2*>(&Wcs[sb * 34 + sc + 2]) = make_float2(w.z, w.w);
            }
        }
        __syncthreads();
        const float* Wt = WRES ? Ws : Wcs;
        const int ws = WRES ? wstr : 34;
        const int wo = WRES ? (k0 - kbeg) : 0;
#pragma unroll
        for (int kk = 0; kk < 16; kk++) {
            ull a0 = *reinterpret_cast<const ull*>(&Hs[ty * 34 + 2 * kk]);
            ull a1 = *reinterpret_cast<const ull*>(&Hs[(ty + 16) * 34 + 2 * kk]);
            ull b0 = *reinterpret_cast<const ull*>(&Wt[tx * ws + wo + 2 * kk]);
            ull b1 = *reinterpret_cast<const ull*>(&Wt[(tx + 16) * ws + wo + 2 * kk]);
            fma2(acc[0][0], a0, b0); fma2(acc[0][1], a0, b1);
            fma2(acc[1][0], a1, b0); fma2(acc[1][1], a1, b1);
        }
    }
}

// ---------------- persistent encoder: 64 steps, Whh slice resident ----------------
__global__ void __launch_bounds__(256) enc_persist(const float* __restrict__ Whh)
{
    extern __shared__ __align__(16) float sm[];
    float* Ws = sm;                 // 32 x 1026
    float* Hs = sm + 32 * 1026;     // 32 x 34

    const int tid = threadIdx.x, bx = blockIdx.x;
    const int tx = tid & 15, ty = tid >> 4;
    const int bn = bx * 32;

    for (int i = tid; i < 8192; i += 256) {
        int r = i >> 8, c4 = (i & 255) * 4;
        float4 v = *reinterpret_cast<const float4*>(Whh + (size_t)(bn + r) * HH + c4);
        *reinterpret_cast<float2*>(&Ws[r * 1026 + c4])     = make_float2(v.x, v.y);
        *reinterpret_cast<float2*>(&Ws[r * 1026 + c4 + 2]) = make_float2(v.z, v.w);
    }
    const int e = bx * 256 + tid;
    const int eb = e >> 10, ej = e & 1023;
    float creg = 0.f;
    const float bi = g_encb[ej], bf = g_encb[ej + 1024],
                bg = g_encb[ej + 2048], bo = g_encb[ej + 3072];
    __syncthreads();

    for (int s = 0; s < SS; s++) {
        ull acc[2][2] = {{0ull, 0ull}, {0ull, 0ull}};
        gemm32<true>(g_h, nullptr, 0, Hs, Ws, 1026, nullptr, 0, 32, acc, tid);
        g_gates[(size_t)ty * H4 + bn + tx]             = lohi(acc[0][0]);
        g_gates[(size_t)ty * H4 + bn + tx + 16]        = lohi(acc[0][1]);
        g_gates[(size_t)(ty + 16) * H4 + bn + tx]      = lohi(acc[1][0]);
        g_gates[(size_t)(ty + 16) * H4 + bn + tx + 16] = lohi(acc[1][1]);
        gbar();
        const float* xg = g_enc_xg + ((size_t)s * BB + eb) * H4;
        float gi = __ldcg(&g_gates[(size_t)eb * H4 + ej])        + bi + xg[ej];
        float gf = __ldcg(&g_gates[(size_t)eb * H4 + ej + 1024]) + bf + xg[ej + 1024];
        float gg = __ldcg(&g_gates[(size_t)eb * H4 + ej + 2048]) + bg + xg[ej + 2048];
        float go = __ldcg(&g_gates[(size_t)eb * H4 + ej + 3072]) + bo + xg[ej + 3072];
        float cn = sigf(gf) * creg + sigf(gi) * tanhf(gg);
        float hn = sigf(go) * tanhf(cn);
        creg = cn;
        g_h[e] = hn;
        g_c[e] = cn;
        g_enc_out[(size_t)eb * SS * HH + (size_t)s * HH + ej] = hn;
        gbar();
    }
}

// ---------------- persistent decoder: 63 steps ----------------
__global__ void __launch_bounds__(256)
dec_persist(const float* __restrict__ attn_W, const float* __restrict__ v_W,
            const float* __restrict__ dec_Wih, const float* __restrict__ dec_Whh)
{
    extern __shared__ __align__(16) float sm[];
    float* Ws2 = sm;                   // 32 x 1026 : dec_Whh slice
    float* Ws1 = Ws2 + 32 * 1026;      // 32 x 258  : Wh (n-tile, k-chunk) slice
    float* Hs  = Ws1 + 32 * 258;       // 32 x 34
    float* Wcs = Hs + 32 * 34;         // 32 x 34
    float* sv  = Wcs + 32 * 34;        // 1024
    float* hWs = sv + 1024;            // 1024
    float* ps  = hWs + 1024;           // 64

    const int tid = threadIdx.x, bx = blockIdx.x;
    const int tx = tid & 15, ty = tid >> 4;
    const int bn  = bx * 32;            // P3 gate-col tile
    const int bn1 = (bx & 31) * 32;     // P1 n-tile
    const int kc1 = bx >> 5;            // P1 k-chunk (256 wide)
    const int ab = bx >> 2, aq = bx & 3;
    const int lane = tid & 31, wrp = tid >> 5;

    for (int i = tid; i < 8192; i += 256) {
        int r = i >> 8, c4 = (i & 255) * 4;
        float4 v = *reinterpret_cast<const float4*>(dec_Whh + (size_t)(bn + r) * HH + c4);
        *reinterpret_cast<float2*>(&Ws2[r * 1026 + c4])     = make_float2(v.x, v.y);
        *reinterpret_cast<float2*>(&Ws2[r * 1026 + c4 + 2]) = make_float2(v.z, v.w);
    }
    for (int i = tid; i < 2048; i += 256) {
        int r = i >> 6, c4 = (i & 63) * 4;
        float4 v = *reinterpret_cast<const float4*>(attn_W + (size_t)(bn1 + r) * (2 * HH) + kc1 * 256 + c4);
        *reinterpret_cast<float2*>(&Ws1[r * 258 + c4])     = make_float2(v.x, v.y);
        *reinterpret_cast<float2*>(&Ws1[r * 258 + c4 + 2]) = make_float2(v.z, v.w);
    }
    for (int i = tid; i < 1024; i += 256) sv[i] = v_W[i];

    const int e = bx * 256 + tid;
    const int eb = e >> 10, ej = e & 1023;
    float creg = g_c[e];
    const float bi = g_decb[ej], bf = g_decb[ej + 1024],
                bg = g_decb[ej + 2048], bo = g_decb[ej + 3072];
    __syncthreads();

    for (int d = 0; d < TT - 1; d++) {
        // P1: hW partial tile (bn1 cols, k-chunk kc1)
        {
            ull a1[2][2] = {{0ull, 0ull}, {0ull, 0ull}};
            gemm32<true>(g_h, nullptr, 0, Hs, Ws1, 258, nullptr, kc1 * 256, 8, a1, tid);
            float* dst = g_hw4 + (size_t)kc1 * BB * HH;
            dst[(size_t)ty * HH + bn1 + tx]             = lohi(a1[0][0]);
            dst[(size_t)ty * HH + bn1 + tx + 16]        = lohi(a1[0][1]);
            dst[(size_t)(ty + 16) * HH + bn1 + tx]      = lohi(a1[1][0]);
            dst[(size_t)(ty + 16) * HH + bn1 + tx + 16] = lohi(a1[1][1]);
        }
        gbar();
        // P2a: reduce hW partials to smem, then tanh scores for 16 s
        {
            int j4 = tid * 4;
            float4 s0 = __ldcg(reinterpret_cast<const float4*>(&g_hw4[(size_t)ab * HH + j4]));
            float4 s1 = __ldcg(reinterpret_cast<const float4*>(&g_hw4[(size_t)(BB + ab) * HH + j4]));
            float4 s2 = __ldcg(reinterpret_cast<const float4*>(&g_hw4[(size_t)(2 * BB + ab) * HH + j4]));
            float4 s3 = __ldcg(reinterpret_cast<const float4*>(&g_hw4[(size_t)(3 * BB + ab) * HH + j4]));
            *reinterpret_cast<float4*>(&hWs[j4]) =
                make_float4(s0.x + s1.x + s2.x + s3.x, s0.y + s1.y + s2.y + s3.y,
                            s0.z + s1.z + s2.z + s3.z, s0.w + s1.w + s2.w + s3.w);
            __syncthreads();
#pragma unroll
            for (int si = 0; si < 2; si++) {
                int s = aq * 16 + wrp * 2 + si;
                float acc = 0.f;
                const float* ep = g_enc_pre + ((size_t)ab * SS + s) * HH;
#pragma unroll
                for (int t = 0; t < 8; t++) {
                    int j = lane * 4 + t * 128;
                    float4 epv = *reinterpret_cast<const float4*>(ep + j);
                    float4 hv  = *reinterpret_cast<const float4*>(&hWs[j]);
                    float4 vv  = *reinterpret_cast<const float4*>(&sv[j]);
                    acc += vv.x * tanh_fast(hv.x + epv.x) + vv.y * tanh_fast(hv.y + epv.y)
                         + vv.z * tanh_fast(hv.z + epv.z) + vv.w * tanh_fast(hv.w + epv.w);
                }
#pragma unroll
                for (int o = 16; o; o >>= 1) acc += __shfl_xor_sync(0xffffffffu, acc, o);
                if (lane == 0) g_sc[ab * SS + s] = acc;
            }
        }
        gbar();
        // P2b: softmax (redundant per q-block) + context quarter
        if (tid < 32) {
            float v0 = __ldcg(&g_sc[ab * SS + tid]);
            float v1 = __ldcg(&g_sc[ab * SS + 32 + tid]);
            float m = fmaxf(v0, v1);
#pragma unroll
            for (int o = 16; o; o >>= 1) m = fmaxf(m, __shfl_xor_sync(0xffffffffu, m, o));
            float e0 = expf(v0 - m), e1 = expf(v1 - m);
            float su = e0 + e1;
#pragma unroll
            for (int o = 16; o; o >>= 1) su += __shfl_xor_sync(0xffffffffu, su, o);
            float inv = 1.f / su;
            ps[tid] = e0 * inv; ps[tid + 32] = e1 * inv;
        }
        __syncthreads();
        {
            int j0 = aq * 256 + tid;
            float acc = 0.f;
            const float* eo = g_enc_out + (size_t)ab * SS * HH + j0;
#pragma unroll 8
            for (int s2 = 0; s2 < SS; s2++) acc += ps[s2] * eo[(size_t)s2 * HH];
            g_ctx[ab * HH + j0] = acc;
        }
        gbar();
        // P3: gates = ctx@Wc^T (streamed) + h@Whh^T (resident)
        {
            ull a3[2][2] = {{0ull, 0ull}, {0ull, 0ull}};
            gemm32<false>(g_ctx, dec_Wih + (size_t)bn * (EE + HH) + EE, EE + HH,
                          Hs, nullptr, 0, Wcs, 0, 32, a3, tid);
            gemm32<true>(g_h, nullptr, 0, Hs, Ws2, 1026, nullptr, 0, 32, a3, tid);
            g_gates[(size_t)ty * H4 + bn + tx]             = lohi(a3[0][0]);
            g_gates[(size_t)ty * H4 + bn + tx + 16]        = lohi(a3[0][1]);
            g_gates[(size_t)(ty + 16) * H4 + bn + tx]      = lohi(a3[1][0]);
            g_gates[(size_t)(ty + 16) * H4 + bn + tx + 16] = lohi(a3[1][1]);
        }
        gbar();
        // P4: LSTM cell
        {
            const float* xg = g_dxg + ((size_t)d * BB + eb) * H4;
            float gi = __ldcg(&g_gates[(size_t)eb * H4 + ej])        + bi + xg[ej];
            float gf = __ldcg(&g_gates[(size_t)eb * H4 + ej + 1024]) + bf + xg[ej + 1024];
            float gg = __ldcg(&g_gates[(size_t)eb * H4 + ej + 2048]) + bg + xg[ej + 2048];
            float go = __ldcg(&g_gates[(size_t)eb * H4 + ej + 3072]) + bo + xg[ej + 3072];
            float cn = sigf(gf) * creg + sigf(gi) * tanhf(gg);
            float hn = sigf(go) * tanhf(cn);
            creg = cn;
            g_h[e] = hn;
            g_hhist[(size_t)d * BB * HH + e] = hn;
        }
        gbar();
    }
}

// ------------------------------------- launch -----------------------------------------
extern "C" void kernel_launch(void* const* d_in, const int* in_sizes, int n_in,
                              void* d_out, int out_size)
{
    const int*   src     = (const int*)d_in[0];
    const int*   tgt     = (const int*)d_in[1];
    const float* enc_emb = (const float*)d_in[2];
    const float* enc_Wih = (const float*)d_in[3];
    const float* enc_Whh = (const float*)d_in[4];
    const float* enc_bih = (const float*)d_in[5];
    const float* enc_bhh = (const float*)d_in[6];
    const float* dec_emb = (const float*)d_in[7];
    const float* attn_W  = (const float*)d_in[8];
    const float* attn_b  = (const float*)d_in[9];
    const float* v_W     = (const float*)d_in[10];
    const float* dec_Wih = (const float*)d_in[11];
    const float* dec_Whh = (const float*)d_in[12];
    const float* dec_bih = (const float*)d_in[13];
    const float* dec_bhh = (const float*)d_in[14];
    const float* fc_W    = (const float*)d_in[15];
    const float* fc_b    = (const float*)d_in[16];
    float* out = (float*)d_out;

    void *pxg, *pdxg, *peo, *pep, *phh, *psi, *pti;
    cudaGetSymbolAddress(&pxg,  g_enc_xg);
    cudaGetSymbolAddress(&pdxg, g_dxg);
    cudaGetSymbolAddress(&peo,  g_enc_out);
    cudaGetSymbolAddress(&pep,  g_enc_pre);
    cudaGetSymbolAddress(&phh,  g_hhist);
    cudaGetSymbolAddress(&psi,  g_sidx);
    cudaGetSymbolAddress(&pti,  g_tidx);
    float* f_xg  = (float*)pxg;   float* f_dxg = (float*)pdxg;
    float* f_eo  = (float*)peo;   float* f_ep  = (float*)pep;
    float* f_hh  = (float*)phh;
    int*   i_si  = (int*)psi;     int*   i_ti  = (int*)pti;

    const int enc_smem = (32 * 1026 + 32 * 34) * 4;
    const int dec_smem = (32 * 1026 + 32 * 258 + 2 * 32 * 34 + 1024 + 1024 + 64) * 4;
    static int configured = 0;
    if (!configured) {
        cudaFuncSetAttribute(enc_persist, cudaFuncAttributeMaxDynamicSharedMemorySize, enc_smem);
        cudaFuncSetAttribute(dec_persist, cudaFuncAttributeMaxDynamicSharedMemorySize, dec_smem);
        configured = 1;
    }

    // 1. init
    init_kernel<<<(BB * VTV + 255) / 256, 256>>>(out, src, tgt,
                                                 enc_bih, enc_bhh, dec_bih, dec_bhh);
    // 2/3. batched input-gate precomputes
    {
        dim3 grid(H4 / 64, (SS * BB + 127) / 128);
        gemm_big<0, true><<<grid, 256>>>(enc_emb, EE, enc_Wih, EE,
                                         f_xg, H4, SS * BB, H4, EE, nullptr, i_si);
    }
    {
        dim3 grid(H4 / 64, ((TT - 1) * BB + 127) / 128);
        gemm_big<0, true><<<grid, 256>>>(dec_emb, EE, dec_Wih, EE + HH,
                                         f_dxg, H4, (TT - 1) * BB, H4, EE, nullptr, i_ti);
    }
    // 4. encoder (persistent)
    enc_persist<<<NBK, 256, enc_smem>>>(enc_Whh);
    // 5. enc_pre = enc_out @ We^T + attn_b
    {
        dim3 grid(HH / 64, (BB * SS + 127) / 128);
        gemm_big<1, false><<<grid, 256>>>(f_eo, HH, attn_W + HH, 2 * HH,
                                          f_ep, HH, BB * SS, HH, HH, attn_b, nullptr);
    }
    // 6. decoder (persistent)
    dec_persist<<<NBK, 256, dec_smem>>>(attn_W, v_W, dec_Wih, dec_Whh);
    // 7. fc logits
    {
        dim3 grid(VTV / 64, ((TT - 1) * BB + 127) / 128);
        gemm_big<4, false><<<grid, 256>>>(f_hh, HH, fc_W, HH,
                                          out, VTV, (TT - 1) * BB, VTV, HH, fc_b, nullptr);
    }
}